// round 4
// baseline (speedup 1.0000x reference)
#include <cuda_runtime.h>
#include <cstdint>

#define VOCAB 30522
#define ROWL  (2*VOCAB)            // 61044 floats per W row (streamed as ONE range)
#define KDIM  2048
#define TOPKN 32
#define NOUT  18
#define BATCH 256
#define SEQ   128
#define KC    7                    // k-rows per block -> grid 293 (one wave @ occ>=2)
#define CW    512                  // columns per chunk
#define NCH   ((ROWL + CW - 1) / CW)   // 120 chunks over the FULL row
#define STAGES 3
#define GRID_SPMM ((KDIM + KC - 1) / KC)   // 293
#define SENT  0x3FFFFFFF

// ---------------- global scratch ----------------
__device__ float g_acts[BATCH * KDIM];              // 2 MB
__device__ int   g_pos[BATCH * 2 * SEQ];            // sorted positions in [0, 2*VOCAB), sentinel-padded
__device__ int   g_pstart[BATCH * (NCH + 1)];       // per-batch chunk start offsets

// ---------------- kernel 1: sort ids, emit 256 sorted positions + chunk offsets ----------------
__global__ void k_sort(const int* __restrict__ ids) {
    __shared__ int s[SEQ];
    __shared__ int p2[2 * SEQ];
    __shared__ int s_n;
    const int b = blockIdx.x;
    const int t = threadIdx.x;                 // 128 threads

    const int id  = ids[b * SEQ + t];
    const int key = (id == 0) ? SENT : id;     // id==0 is padding: contributes nothing
    s[t] = key;
    if (t == 0) s_n = 0;
    __syncthreads();

    int rank = 0;
    #pragma unroll 16
    for (int j = 0; j < SEQ; j++) {
        const int kj = s[j];
        rank += (kj < key) || (kj == key && j < t);   // stable unique ranks
    }
    if (key != SENT) atomicAdd(&s_n, 1);
    p2[t] = SENT; p2[t + SEQ] = SENT;
    __syncthreads();

    const int n = s_n;                         // nonzero count; real keys have rank < n
    if (key != SENT) {
        p2[rank]     = key;                    // lower-half position
        p2[rank + n] = key + VOCAB;            // upper-half position (still sorted globally)
    }
    __syncthreads();

    g_pos[b * 2 * SEQ + t]       = p2[t];
    g_pos[b * 2 * SEQ + t + SEQ] = p2[t + SEQ];

    if (t <= NCH) {                            // pstart[ch] = #positions < ch*CW
        const int target = t * CW;
        int lo = 0, hi = 2 * SEQ;
        while (lo < hi) {
            const int m = (lo + hi) >> 1;
            if (p2[m] < target) lo = m + 1; else hi = m;
        }
        g_pstart[b * (NCH + 1) + t] = lo;
    }
}

// ---------------- kernel 2: cp.async 3-stage pipelined stream of W ----------------
__device__ __forceinline__ void cp16(uint32_t dst, const float* src) {
    asm volatile("cp.async.cg.shared.global [%0], [%1], 16;" :: "r"(dst), "l"(src));
}
__device__ __forceinline__ void cp_commit() {
    asm volatile("cp.async.commit_group;" ::: "memory");
}
__device__ __forceinline__ void cp_wait2() {
    asm volatile("cp.async.wait_group 2;" ::: "memory");
}

__global__ __launch_bounds__(256) void k_spmm(const float* __restrict__ W) {
    __shared__ __align__(16) float s_w[STAGES * KC * CW];   // 42 KB
    const int k0   = blockIdx.x * KC;
    const int rows = (KDIM - k0 < KC) ? (KDIM - k0) : KC;   // last block: 4 rows
    const int b    = threadIdx.x;                            // thread <-> batch
    const uint32_t s_base = (uint32_t)__cvta_generic_to_shared(s_w);

    float acc[KC];
    #pragma unroll
    for (int j = 0; j < KC; j++) acc[j] = 0.f;

    const int* __restrict__ mypos = g_pos    + b * 2 * SEQ;
    const int* __restrict__ pst   = g_pstart + b * (NCH + 1);

    const int nq = rows * (CW / 4);            // 16B quads per chunk (<= 896)

    // prologue: fill STAGES stages
    #pragma unroll
    for (int st = 0; st < STAGES; st++) {
        const int c0 = st * CW;
        for (int o = b; o < nq; o += 256) {
            const int j = o >> 7, cc4 = o & 127;
            const int c = c0 + 4 * cc4;
            if (c < ROWL)
                cp16(s_base + (uint32_t)(st * KC * CW + j * CW + 4 * cc4) * 4,
                     W + (size_t)(k0 + j) * ROWL + c);
        }
        cp_commit();
    }

    int p = 0;
    for (int ch = 0; ch < NCH; ch++) {
        cp_wait2();                            // oldest group landed
        __syncthreads();

        const int st = ch % STAGES;
        const float* smc = s_w + st * KC * CW;
        const int c0 = ch * CW;
        const int pend = pst[ch + 1];

        // consume in groups of 4 positions: independent id loads, fewer issues
        while (p + 4 <= pend) {
            const int cc0 = mypos[p]     - c0;
            const int cc1 = mypos[p + 1] - c0;
            const int cc2 = mypos[p + 2] - c0;
            const int cc3 = mypos[p + 3] - c0;
            #pragma unroll
            for (int j = 0; j < KC; j++)
                acc[j] += (smc[j * CW + cc0] + smc[j * CW + cc1])
                        + (smc[j * CW + cc2] + smc[j * CW + cc3]);
            p += 4;
        }
        for (; p < pend; ++p) {
            const int cc = mypos[p] - c0;
            #pragma unroll
            for (int j = 0; j < KC; j++) acc[j] += smc[j * CW + cc];
        }
        __syncthreads();                       // everyone done with this stage

        const int nch = ch + STAGES;           // refill this stage
        if (nch < NCH) {
            const int nc0 = nch * CW;
            for (int o = b; o < nq; o += 256) {
                const int j = o >> 7, cc4 = o & 127;
                const int c = nc0 + 4 * cc4;
                if (c < ROWL)
                    cp16(s_base + (uint32_t)(st * KC * CW + j * CW + 4 * cc4) * 4,
                         W + (size_t)(k0 + j) * ROWL + c);
            }
        }
        cp_commit();                           // always commit (keeps wait accounting)
    }

    for (int j = 0; j < rows; j++)
        g_acts[(size_t)b * KDIM + k0 + j] = acc[j];
}

// ---------------- kernel 3: exact fp32 top-32 + logits ----------------
__global__ void k_topk(const float* __restrict__ Wa, const float* __restrict__ ba,
                       float* __restrict__ out) {
    __shared__ float rv[8];
    __shared__ int   ri[8];
    __shared__ int   s_sel[TOPKN];
    __shared__ int   s_idx;
    const int b = blockIdx.x;
    const int t = threadIdx.x;                 // 256 threads
    const int lane = t & 31, wid = t >> 5;

    float v[8];
    #pragma unroll
    for (int i = 0; i < 8; i++) v[i] = g_acts[(size_t)b * KDIM + t + i * 256];

    for (int it = 0; it < TOPKN; it++) {
        float bv = v[0]; int bi = t;
        #pragma unroll
        for (int i = 1; i < 8; i++) {
            const int idx = t + i * 256;
            if (v[i] > bv || (v[i] == bv && idx < bi)) { bv = v[i]; bi = idx; }
        }
        #pragma unroll
        for (int o = 16; o > 0; o >>= 1) {     // warp argmax, jax tie-break (lower idx)
            const float ov = __shfl_down_sync(0xffffffff, bv, o);
            const int   oi = __shfl_down_sync(0xffffffff, bi, o);
            if (ov > bv || (ov == bv && oi < bi)) { bv = ov; bi = oi; }
        }
        if (lane == 0) { rv[wid] = bv; ri[wid] = bi; }
        __syncthreads();
        if (t == 0) {
            float mv = rv[0]; int mi = ri[0];
            #pragma unroll
            for (int w = 1; w < 8; w++)
                if (rv[w] > mv || (rv[w] == mv && ri[w] < mi)) { mv = rv[w]; mi = ri[w]; }
            s_idx = mi; s_sel[it] = mi;
        }
        __syncthreads();
        const int mi = s_idx;
        if ((mi & 255) == t) v[mi >> 8] = -3.402823466e38f;   // remove selected
    }
    __syncthreads();

    if (t < NOUT) {
        float s = ba[t];
        #pragma unroll
        for (int i = 0; i < TOPKN; i++) s += Wa[(size_t)t * KDIM + s_sel[i]];
        out[(size_t)b * NOUT + t] = s;
    }
}

// ---------------- launch ----------------
extern "C" void kernel_launch(void* const* d_in, const int* in_sizes, int n_in,
                              void* d_out, int out_size) {
    const int*   ids = (const int*)d_in[0];
    const float* W   = (const float*)d_in[1];
    const float* Wa  = (const float*)d_in[2];
    const float* ba  = (const float*)d_in[3];
    float*       out = (float*)d_out;

    k_sort<<<BATCH, SEQ>>>(ids);
    k_spmm<<<GRID_SPMM, BATCH>>>(W);
    k_topk<<<BATCH, BATCH>>>(Wa, ba, out);
}

// round 12
// speedup vs baseline: 1.1238x; 1.1238x over previous
#include <cuda_runtime.h>
#include <cstdint>

#define VOCAB 30522
#define ROWL  (2*VOCAB)            // 61044 floats per W row, streamed as one range
#define KDIM  2048
#define TOPKN 32
#define NOUT  18
#define BATCH 256
#define SEQ   128
#define KC    7                    // k-rows per block -> grid 293 (one resident wave)
#define CW    512                  // columns per chunk
#define NCH   ((ROWL + CW - 1) / CW)   // 120
#define STAGES 3
#define GRID_SPMM ((KDIM + KC - 1) / KC)   // 293
#define SENT  0x3FFFFFFF

// ---------------- global scratch ----------------
__device__ float g_acts[BATCH * KDIM];
__device__ int   g_pos[BATCH * 2 * SEQ];       // sorted positions in [0, 2*VOCAB), sentinel-padded
__device__ int   g_pstart[BATCH * (NCH + 1)];  // per-batch chunk start offsets

// ---------------- PTX helpers ----------------
__device__ __forceinline__ uint32_t smem_u32(const void* p) {
    return (uint32_t)__cvta_generic_to_shared(p);
}
__device__ __forceinline__ void mbar_init(uint32_t mbar, uint32_t cnt) {
    asm volatile("mbarrier.init.shared.b64 [%0], %1;" :: "r"(mbar), "r"(cnt) : "memory");
}
__device__ __forceinline__ void mbar_expect_tx(uint32_t mbar, uint32_t bytes) {
    asm volatile("mbarrier.arrive.expect_tx.shared.b64 _, [%0], %1;" :: "r"(mbar), "r"(bytes) : "memory");
}
__device__ __forceinline__ void mbar_arrive(uint32_t mbar) {
    asm volatile("mbarrier.arrive.shared.b64 _, [%0];" :: "r"(mbar) : "memory");
}
__device__ __forceinline__ void mbar_wait_acq(uint32_t mbar, uint32_t parity) {
    uint32_t done;
    asm volatile("{\n\t.reg .pred p;\n\t"
                 "mbarrier.try_wait.parity.acquire.cta.shared::cta.b64 p, [%1], %2;\n\t"
                 "selp.b32 %0, 1, 0, p;\n\t}"
                 : "=r"(done) : "r"(mbar), "r"(parity) : "memory");
    if (!done) {
        asm volatile("{\n\t.reg .pred P1;\n\t"
                     "W0_%=:\n\t"
                     "mbarrier.try_wait.parity.acquire.cta.shared::cta.b64 P1, [%0], %1, 0x989680;\n\t"
                     "@P1 bra.uni W1_%=;\n\t"
                     "bra.uni W0_%=;\n\t"
                     "W1_%=:\n\t}"
                     :: "r"(mbar), "r"(parity) : "memory");
    }
}
__device__ __forceinline__ void mbar_wait_rlx(uint32_t mbar, uint32_t parity) {
    uint32_t done;
    asm volatile("{\n\t.reg .pred p;\n\t"
                 "mbarrier.try_wait.parity.relaxed.cta.shared::cta.b64 p, [%1], %2, 0x989680;\n\t"
                 "selp.b32 %0, 1, 0, p;\n\t}"
                 : "=r"(done) : "r"(mbar), "r"(parity) : "memory");
    if (!done) {
        asm volatile("{\n\t.reg .pred P1;\n\t"
                     "W0_%=:\n\t"
                     "mbarrier.try_wait.parity.relaxed.cta.shared::cta.b64 P1, [%0], %1, 0x989680;\n\t"
                     "@P1 bra.uni W1_%=;\n\t"
                     "bra.uni W0_%=;\n\t"
                     "W1_%=:\n\t}"
                     :: "r"(mbar), "r"(parity) : "memory");
    }
}
__device__ __forceinline__ void tma_bulk_1d(uint32_t dst, const void* src, uint32_t bytes, uint32_t mbar) {
    asm volatile("cp.async.bulk.shared::cta.global.mbarrier::complete_tx::bytes [%0], [%1], %2, [%3];"
                 :: "r"(dst), "l"(src), "r"(bytes), "r"(mbar) : "memory");
}

// ---------------- kernel 1: sort ids, emit sorted positions + chunk offsets ----------------
__global__ void k_sort(const int* __restrict__ ids) {
    __shared__ int s[SEQ];
    __shared__ int p2[2 * SEQ];
    __shared__ int s_n;
    const int b = blockIdx.x;
    const int t = threadIdx.x;                 // 128 threads

    const int id  = ids[b * SEQ + t];
    const int key = (id == 0) ? SENT : id;     // id==0 is padding
    s[t] = key;
    if (t == 0) s_n = 0;
    __syncthreads();

    int rank = 0;
    #pragma unroll 16
    for (int j = 0; j < SEQ; j++) {
        const int kj = s[j];
        rank += (kj < key) || (kj == key && j < t);   // stable unique ranks
    }
    if (key != SENT) atomicAdd(&s_n, 1);
    p2[t] = SENT; p2[t + SEQ] = SENT;
    __syncthreads();

    const int n = s_n;
    if (key != SENT) {
        p2[rank]     = key;                    // lower-half position
        p2[rank + n] = key + VOCAB;            // upper-half (globally sorted)
    }
    __syncthreads();

    g_pos[b * 2 * SEQ + t]       = p2[t];
    g_pos[b * 2 * SEQ + t + SEQ] = p2[t + SEQ];

    if (t <= NCH) {                            // pstart[ch] = #positions < ch*CW
        const int target = t * CW;
        int lo = 0, hi = 2 * SEQ;
        while (lo < hi) {
            const int m = (lo + hi) >> 1;
            if (p2[m] < target) lo = m + 1; else hi = m;
        }
        g_pstart[b * (NCH + 1) + t] = lo;
    }
}

// ---------------- kernel 2: TMA-pipelined stream of W, barrier-free consume ----------------
__global__ __launch_bounds__(256) void k_spmm(const float* __restrict__ W) {
    __shared__ __align__(16) float s_w[STAGES * KC * CW];                // 42 KB
    __shared__ __align__(8) unsigned long long s_full[STAGES], s_empty[STAGES];
    const int k0   = blockIdx.x * KC;
    const int rows = (KDIM - k0 < KC) ? (KDIM - k0) : KC;               // last block: 4
    const int t    = threadIdx.x;                                       // thread <-> batch
    const uint32_t w_base  = smem_u32(s_w);
    const uint32_t full_b  = smem_u32(s_full);
    const uint32_t empty_b = smem_u32(s_empty);

    if (t == 0) {
        #pragma unroll
        for (int st = 0; st < STAGES; st++) {
            mbar_init(full_b  + 8u * st, 1);    // 1 expect_tx arrival + tx bytes
            mbar_init(empty_b + 8u * st, 256);  // all consumers
        }
    }
    __syncthreads();

    // producer prologue: fill all stages
    if (t == 0) {
        #pragma unroll
        for (int st = 0; st < STAGES; st++) {
            const int c0 = st * CW;
            const int cols = (ROWL - c0 < CW) ? (ROWL - c0) : CW;
            const uint32_t rb = (uint32_t)cols * 4u;
            mbar_expect_tx(full_b + 8u * st, (uint32_t)rows * rb);
            for (int j = 0; j < rows; j++)
                tma_bulk_1d(w_base + (uint32_t)(st * KC * CW + j * CW) * 4u,
                            W + (size_t)(k0 + j) * ROWL + c0, rb, full_b + 8u * st);
        }
    }

    float acc[KC];
    #pragma unroll
    for (int j = 0; j < KC; j++) acc[j] = 0.f;

    const int* __restrict__ mypos = g_pos    + t * 2 * SEQ;
    const int* __restrict__ pst   = g_pstart + t * (NCH + 1);
    int p = 0;

    for (int ch = 0; ch < NCH; ch++) {
        const int st = ch % STAGES;
        const int u  = ch / STAGES;
        mbar_wait_acq(full_b + 8u * st, u & 1);          // stage data landed

        const float* smc = s_w + st * KC * CW;
        const int c0 = ch * CW;
        const int pend = pst[ch + 1];
        while (p + 2 <= pend) {
            const int cc0 = mypos[p]     - c0;
            const int cc1 = mypos[p + 1] - c0;
            #pragma unroll
            for (int j = 0; j < KC; j++)
                acc[j] += smc[j * CW + cc0] + smc[j * CW + cc1];
            p += 2;
        }
        if (p < pend) {
            const int cc = mypos[p] - c0;
            #pragma unroll
            for (int j = 0; j < KC; j++) acc[j] += smc[j * CW + cc];
            ++p;
        }

        mbar_arrive(empty_b + 8u * st);                  // done with this stage

        if (t == 0 && ch + STAGES < NCH) {               // producer refill
            mbar_wait_rlx(empty_b + 8u * st, u & 1);     // all 256 done with use u
            const int nc0 = (ch + STAGES) * CW;
            const int cols = (ROWL - nc0 < CW) ? (ROWL - nc0) : CW;
            const uint32_t rb = (uint32_t)cols * 4u;
            mbar_expect_tx(full_b + 8u * st, (uint32_t)rows * rb);
            for (int j = 0; j < rows; j++)
                tma_bulk_1d(w_base + (uint32_t)(st * KC * CW + j * CW) * 4u,
                            W + (size_t)(k0 + j) * ROWL + nc0, rb, full_b + 8u * st);
        }
    }

    for (int j = 0; j < rows; j++)
        g_acts[(size_t)t * KDIM + k0 + j] = acc[j];
}

// ---------------- kernel 3: exact fp32 top-32 + logits ----------------
__global__ void k_topk(const float* __restrict__ Wa, const float* __restrict__ ba,
                       float* __restrict__ out) {
    __shared__ float rv[8];
    __shared__ int   ri[8];
    __shared__ int   s_sel[TOPKN];
    __shared__ int   s_idx;
    const int b = blockIdx.x;
    const int t = threadIdx.x;                 // 256 threads
    const int lane = t & 31, wid = t >> 5;

    float v[8];
    #pragma unroll
    for (int i = 0; i < 8; i++) v[i] = g_acts[(size_t)b * KDIM + t + i * 256];

    for (int it = 0; it < TOPKN; it++) {
        float bv = v[0]; int bi = t;
        #pragma unroll
        for (int i = 1; i < 8; i++) {
            const int idx = t + i * 256;
            if (v[i] > bv || (v[i] == bv && idx < bi)) { bv = v[i]; bi = idx; }
        }
        #pragma unroll
        for (int o = 16; o > 0; o >>= 1) {     // warp argmax, jax tie-break (lower idx)
            const float ov = __shfl_down_sync(0xffffffff, bv, o);
            const int   oi = __shfl_down_sync(0xffffffff, bi, o);
            if (ov > bv || (ov == bv && oi < bi)) { bv = ov; bi = oi; }
        }
        if (lane == 0) { rv[wid] = bv; ri[wid] = bi; }
        __syncthreads();
        if (t == 0) {
            float mv = rv[0]; int mi = ri[0];
            #pragma unroll
            for (int w = 1; w < 8; w++)
                if (rv[w] > mv || (rv[w] == mv && ri[w] < mi)) { mv = rv[w]; mi = ri[w]; }
            s_idx = mi; s_sel[it] = mi;
        }
        __syncthreads();
        const int mi = s_idx;
        if ((mi & 255) == t) v[mi >> 8] = -3.402823466e38f;   // remove selected
    }
    __syncthreads();

    if (t < NOUT) {
        float s = ba[t];
        #pragma unroll
        for (int i = 0; i < TOPKN; i++) s += Wa[(size_t)t * KDIM + s_sel[i]];
        out[(size_t)b * NOUT + t] = s;
    }
}

// ---------------- launch ----------------
extern "C" void kernel_launch(void* const* d_in, const int* in_sizes, int n_in,
                              void* d_out, int out_size) {
    const int*   ids = (const int*)d_in[0];
    const float* W   = (const float*)d_in[1];
    const float* Wa  = (const float*)d_in[2];
    const float* ba  = (const float*)d_in[3];
    float*       out = (float*)d_out;

    k_sort<<<BATCH, SEQ>>>(ids);
    k_spmm<<<GRID_SPMM, BATCH>>>(W);
    k_topk<<<BATCH, BATCH>>>(Wa, ba, out);
}